// round 17
// baseline (speedup 1.0000x reference)
#include <cuda_runtime.h>
#include <cstdint>

#define T_STEPS 1000
#define BATCH   2048
#define FEAT    40
#define H1      8
#define H2      6
#define G1      32

#define CT      10
#define NCHUNK  (T_STEPS / CT)      // 100
#define XBYTES  (CT * FEAT * 4)     // 1600 B per chunk

typedef unsigned long long u64;

// ---------------- helpers ----------------
__device__ __forceinline__ u64 pack2(float x, float y) {
    u64 r; asm("mov.b64 %0, {%1, %2};" : "=l"(r) : "f"(x), "f"(y)); return r;
}
__device__ __forceinline__ void unpack2(u64 v, float& x, float& y) {
    asm("mov.b64 {%0, %1}, %2;" : "=f"(x), "=f"(y) : "l"(v));
}
__device__ __forceinline__ u64 fma2(u64 a, u64 b, u64 c) {
    u64 d; asm("fma.rn.f32x2 %0, %1, %2, %3;" : "=l"(d) : "l"(a), "l"(b), "l"(c)); return d;
}
__device__ __forceinline__ u64 mul2(u64 a, u64 b) {
    u64 d; asm("mul.rn.f32x2 %0, %1, %2;" : "=l"(d) : "l"(a), "l"(b)); return d;
}
__device__ __forceinline__ u64 add2(u64 a, u64 b) {
    u64 d; asm("add.rn.f32x2 %0, %1, %2;" : "=l"(d) : "l"(a), "l"(b)); return d;
}
__device__ __forceinline__ u64 scale2(u64 v, float s) {
    float a, b; unpack2(v, a, b); return pack2(a * s, b * s);
}
__device__ __forceinline__ float hadd2(u64 v) {
    float a, b; unpack2(v, a, b); return a + b;
}
__device__ __forceinline__ float tanha(float x) {
    float r; asm("tanh.approx.f32 %0, %1;" : "=f"(r) : "f"(x)); return r;
}
__device__ __forceinline__ float shflf(float v, int src) {
    return __shfl_sync(0xffffffffu, v, src & 31);
}
__device__ __forceinline__ float shflx(float v, int m) {
    return __shfl_xor_sync(0xffffffffu, v, m);
}
__device__ __forceinline__ uint32_t smem_u32(const void* p) {
    uint32_t a;
    asm("{ .reg .u64 t; cvta.to.shared.u64 t, %1; cvt.u32.u64 %0, t; }" : "=r"(a) : "l"(p));
    return a;
}
// ---- TMA bulk copy + mbarrier (Blackwell path) ----
__device__ __forceinline__ void mbar_init(uint32_t mbar, uint32_t cnt) {
    asm volatile("mbarrier.init.shared.b64 [%0], %1;" :: "r"(mbar), "r"(cnt) : "memory");
}
__device__ __forceinline__ void mbar_expect_tx(uint32_t mbar, uint32_t bytes) {
    asm volatile("mbarrier.arrive.expect_tx.shared.b64 _, [%0], %1;"
                 :: "r"(mbar), "r"(bytes) : "memory");
}
__device__ __forceinline__ void mbar_wait(uint32_t mbar, uint32_t phase) {
    asm volatile(
        "{\n\t"
        ".reg .pred P;\n\t"
        "W%=:\n\t"
        "mbarrier.try_wait.parity.acquire.cta.shared::cta.b64 P, [%0], %1, 0x989680;\n\t"
        "@P bra D%=;\n\t"
        "bra W%=;\n\t"
        "D%=:\n\t"
        "}"
        :: "r"(mbar), "r"(phase) : "memory");
}
__device__ __forceinline__ void bulk_copy(uint32_t dst_smem, const void* src_g,
                                          uint32_t bytes, uint32_t mbar) {
    asm volatile(
        "cp.async.bulk.shared::cta.global.mbarrier::complete_tx::bytes [%0], [%1], %2, [%3];"
        :: "r"(dst_smem), "l"(src_g), "r"(bytes), "r"(mbar) : "memory");
}
__device__ __forceinline__ void fence_proxy_async_cta() {
    asm volatile("fence.proxy.async.shared::cta;" ::: "memory");
}
#define BAR64() asm volatile("bar.sync 0, 64;" ::: "memory")

// ============================================================================
// consumer step (R10/R14/R15 proven, verbatim): layer1(i) + layer2(i-1).
// slab shs[2][24]: [0..7]=h1, [8..15]=x2, [16..21]=h2
// L1 gates at lanes: i 0-7 | f 8-15 | g 16-23 | o 24-31  (c1 on lanes 8-15)
// L2 gates at lanes: i 0-5 | f 8-13 | g 16-21 | o 24-29  (c2 on lanes 8-13)
// ============================================================================
template <int RD>
__device__ __forceinline__ void rec_step(
    float en, int lane, float gval,
    float (*shs)[24],
    const u64* __restrict__ w1p, const u64* __restrict__ wi2p,
    const u64* __restrict__ wh2p, u64 bias2p,
    float cn1, float ca1, float cn2, float ca2,
    float& c1, float& c2)
{
    constexpr int WR = RD ^ 1;

    const ulonglong2* hp = reinterpret_cast<const ulonglong2*>(&shs[RD][0]);
    ulonglong2 h01 = hp[0], h23 = hp[1];   // h1[0..7]
    ulonglong2 x01 = hp[2], x23 = hp[3];   // x2[0..7]
    ulonglong2 h2a = hp[4];                // h2[0..3]
    u64        h2b = reinterpret_cast<const u64*>(&shs[RD][0])[10];  // h2[4..5]

    // layer1: g1 = gval + h1 . w1
    u64 C = mul2(h01.x, w1p[0]);
    C = fma2(h01.y, w1p[1], C);
    u64 D = mul2(h23.x, w1p[2]);
    D = fma2(h23.y, w1p[3], D);
    float g1 = gval + hadd2(add2(C, D));

    // layer2: g2 = bias2 + x2 . wi2 + h2 . wh2
    u64 P = fma2(x01.x, wi2p[0], bias2p);
    u64 Q = mul2(x01.y, wi2p[1]);
    P = fma2(x23.x, wi2p[2], P);
    Q = fma2(x23.y, wi2p[3], Q);
    P = fma2(h2a.x, wh2p[0], P);
    Q = fma2(h2a.y, wh2p[1], Q);
    P = fma2(h2b,   wh2p[2], P);
    float g2 = hadd2(add2(P, Q));

    float a1 = fmaf(cn1, tanha(g1), ca1);
    float a2 = fmaf(cn2, tanha(g2), ca2);

    // XOR gathers
    float s1 = shflx(a1, 16);
    float s2 = shflx(a2, 16);
    float p1 = a1 * s1;
    float p2 = a2 * s2;
    float t1 = shflx(p1, 8);     // lanes 8-15 <- i*g (L1)
    float t2 = shflx(p2, 8);     // lanes 8-13 <- i*g (L2)

    // state owners: lanes 8-15 hold a1=f, s1=o
    c1 = fmaf(a1, c1, t1);
    float h1v = s1 * tanha(c1);
    float x2v = tanha(h1v);

    // lanes 8-13 hold a2=f2, s2=o2
    c2 = en * fmaf(a2, c2, t2);
    float h2v = s2 * tanha(c2);

    if (lane >= 8 && lane < 16) {
        shs[WR][lane - 8] = h1v;   // h1 slot
        shs[WR][lane]     = x2v;   // x2 slot
    }
    if (lane >= 8 && lane < 14) shs[WR][8 + lane] = h2v;   // h2 slot 16+(lane-8)
    __syncwarp();
}

// ============================================================================
// producer chunk: SPLIT-K G=2 (R15/R16 proven). lane = (l, h).
// ============================================================================
__device__ __forceinline__ void produce_chunk(
    const float (*src)[FEAT], float (*dstg)[G1],
    int l, int h,
    const u64* __restrict__ wA, const u64* __restrict__ wB,
    float bias)
{
#pragma unroll
    for (int r = 0; r < CT; r++) {
        const ulonglong2* xr = reinterpret_cast<const ulonglong2*>(&src[r][20 * h]);
        ulonglong2 v0 = xr[0], v1 = xr[1], v2 = xr[2], v3 = xr[3], v4 = xr[4];

        u64 a0 = mul2(wA[0], v0.x);
        u64 a1 = mul2(wA[1], v0.y);
        u64 b0 = mul2(wB[0], v0.x);
        u64 b1 = mul2(wB[1], v0.y);
        a0 = fma2(wA[2], v1.x, a0);
        a1 = fma2(wA[3], v1.y, a1);
        b0 = fma2(wB[2], v1.x, b0);
        b1 = fma2(wB[3], v1.y, b1);
        a0 = fma2(wA[4], v2.x, a0);
        a1 = fma2(wA[5], v2.y, a1);
        b0 = fma2(wB[4], v2.x, b0);
        b1 = fma2(wB[5], v2.y, b1);
        a0 = fma2(wA[6], v3.x, a0);
        a1 = fma2(wA[7], v3.y, a1);
        b0 = fma2(wB[6], v3.x, b0);
        b1 = fma2(wB[7], v3.y, b1);
        a0 = fma2(wA[8], v4.x, a0);
        a1 = fma2(wA[9], v4.y, a1);
        b0 = fma2(wB[8], v4.x, b0);
        b1 = fma2(wB[9], v4.y, b1);

        float pA = hadd2(add2(a0, a1));
        float pB = hadd2(add2(b0, b1));

        float send = h ? pA : pB;
        float recv = shflx(send, 16);
        float full = (h ? pB : pA) + recv + bias;

        dstg[r][l + 16 * h] = full;     // 32 consecutive words: 1 wf
    }
}

// ============================================================================
// fused producer/consumer kernel: 1 block = 1 batch element, 2 warps.
// x staging via cp.async.bulk (1 TMA op per 1600B chunk) + mbarrier.
// ============================================================================
__global__ void __launch_bounds__(64, 14)
fused_pc(const float* __restrict__ x,
         const float* __restrict__ W_ih1,
         const float* __restrict__ W_hh1,
         const float* __restrict__ b_ih1,
         const float* __restrict__ b_hh1,
         const float* __restrict__ W_ih2,
         const float* __restrict__ W_hh2,
         const float* __restrict__ b_ih2,
         const float* __restrict__ b_hh2,
         const float* __restrict__ W_fc,
         const float* __restrict__ b_fc,
         float* __restrict__ out) {
    __shared__ __align__(16) float sgate[2][CT][G1];   // flat gate ring
    __shared__ __align__(16) float sx[2][CT][FEAT];    // x staging (bulk copy)
    __shared__ __align__(16) float shs[2][24];         // hidden slabs
    __shared__ __align__(8)  u64   smbar[2];           // per-buffer mbarriers

    int tid  = threadIdx.x;
    int lane = tid & 31;
    int wid  = tid >> 5;
    int b    = blockIdx.x;

    if (wid == 1) {
        // ============ PRODUCER (split-K G=2 + TMA bulk staging) ============
        int l = lane & 15, h = lane >> 4;
        int gA = l, gB = l + 16;
        float cmA = 0.5f;                     // gates 0..15: sigmoid
        float cmB = (l < 8) ? 1.0f : 0.5f;    // 16..23 tanh, 24..31 sigmoid

        u64 wA[10], wB[10];
        {
            const u64* wra = reinterpret_cast<const u64*>(W_ih1 + gA * FEAT + 20 * h);
            const u64* wrb = reinterpret_cast<const u64*>(W_ih1 + gB * FEAT + 20 * h);
#pragma unroll
            for (int p = 0; p < 10; p++) {
                wA[p] = scale2(wra[p], cmA);
                wB[p] = scale2(wrb[p], cmB);
            }
        }
        float bias = h ? (cmB * (b_ih1[gB] + b_hh1[gB]))
                       : (cmA * (b_ih1[gA] + b_hh1[gA]));

        const char* xb = reinterpret_cast<const char*>(x + (size_t)b * T_STEPS * FEAT);
        uint32_t sxa[2] = { smem_u32(&sx[0][0][0]), smem_u32(&sx[1][0][0]) };
        uint32_t mba[2] = { smem_u32(&smbar[0]), smem_u32(&smbar[1]) };

        if (lane == 0) {
            mbar_init(mba[0], 1);
            mbar_init(mba[1], 1);
            fence_proxy_async_cta();
            // issue chunks 0,1
            mbar_expect_tx(mba[0], XBYTES);
            bulk_copy(sxa[0], xb, XBYTES, mba[0]);
            mbar_expect_tx(mba[1], XBYTES);
            bulk_copy(sxa[1], xb + XBYTES, XBYTES, mba[1]);
        }
        __syncwarp();

        uint32_t ph0 = 0, ph1 = 0;     // per-buffer phase parity

        mbar_wait(mba[0], ph0); ph0 ^= 1;
        produce_chunk(sx[0], sgate[0], l, h, wA, wB, bias);
        BAR64();

#pragma unroll 1
        for (int c = 0; c < NCHUNK; c++) {
            if (c + 2 < NCHUNK && lane == 0) {
                int bf = c & 1;    // buffer holding chunk c (already consumed)
                mbar_expect_tx(mba[bf], XBYTES);
                bulk_copy(sxa[bf], xb + (size_t)(c + 2) * XBYTES, XBYTES, mba[bf]);
            }
            if (c + 1 < NCHUNK) {
                int bn = (c + 1) & 1;
                if (bn == 0) { mbar_wait(mba[0], ph0); ph0 ^= 1; }
                else         { mbar_wait(mba[1], ph1); ph1 ^= 1; }
                produce_chunk(sx[bn], sgate[bn], l, h, wA, wB, bias);
            }
            BAR64();
        }
    } else {
        // ======================= CONSUMER (R15/R16 verbatim) ==================
        bool t1c = ((lane >> 3) == 2);
        float cm1 = t1c ? 1.f : 0.5f, cn1 = t1c ? 1.f : 0.5f, ca1 = t1c ? 0.f : 0.5f;
        bool v2 = ((lane & 7) < 6) && (lane < 30);
        int g2i = lane - 2 * (lane >> 3);
        bool t2c = (lane >= 16 && lane < 22);
        float cm2 = t2c ? 1.f : 0.5f, cn2 = t2c ? 1.f : 0.5f, ca2 = t2c ? 0.f : 0.5f;

        u64 w1p[H1 / 2];
#pragma unroll
        for (int j = 0; j < H1 / 2; j++)
            w1p[j] = pack2(cm1 * W_hh1[lane * H1 + 2 * j], cm1 * W_hh1[lane * H1 + 2 * j + 1]);

        u64 wi2p[H1 / 2], wh2p[H2 / 2], bias2p = 0ull;
#pragma unroll
        for (int j = 0; j < H1 / 2; j++) wi2p[j] = 0ull;
#pragma unroll
        for (int j = 0; j < H2 / 2; j++) wh2p[j] = 0ull;
        if (v2) {
#pragma unroll
            for (int j = 0; j < H1 / 2; j++)
                wi2p[j] = pack2(cm2 * W_ih2[g2i * H1 + 2 * j], cm2 * W_ih2[g2i * H1 + 2 * j + 1]);
#pragma unroll
            for (int j = 0; j < H2 / 2; j++)
                wh2p[j] = pack2(cm2 * W_hh2[g2i * H2 + 2 * j], cm2 * W_hh2[g2i * H2 + 2 * j + 1]);
            bias2p = pack2(cm2 * (b_ih2[g2i] + b_hh2[g2i]), 0.f);
        }

        if (lane < 24) shs[1][lane] = 0.f;
        float c1 = 0.f, c2 = 0.f;
        BAR64();

#pragma unroll 1
        for (int c = 0; c < NCHUNK; c++) {
            const float* gr = &sgate[c & 1][0][0];
            float en0 = (c == 0) ? 0.f : 1.f;

            rec_step<1>(en0, lane, gr[0 * G1 + lane], shs, w1p, wi2p, wh2p, bias2p,
                        cn1, ca1, cn2, ca2, c1, c2);
            rec_step<0>(1.f, lane, gr[1 * G1 + lane], shs, w1p, wi2p, wh2p, bias2p,
                        cn1, ca1, cn2, ca2, c1, c2);
            rec_step<1>(1.f, lane, gr[2 * G1 + lane], shs, w1p, wi2p, wh2p, bias2p,
                        cn1, ca1, cn2, ca2, c1, c2);
            rec_step<0>(1.f, lane, gr[3 * G1 + lane], shs, w1p, wi2p, wh2p, bias2p,
                        cn1, ca1, cn2, ca2, c1, c2);
            rec_step<1>(1.f, lane, gr[4 * G1 + lane], shs, w1p, wi2p, wh2p, bias2p,
                        cn1, ca1, cn2, ca2, c1, c2);
            rec_step<0>(1.f, lane, gr[5 * G1 + lane], shs, w1p, wi2p, wh2p, bias2p,
                        cn1, ca1, cn2, ca2, c1, c2);
            rec_step<1>(1.f, lane, gr[6 * G1 + lane], shs, w1p, wi2p, wh2p, bias2p,
                        cn1, ca1, cn2, ca2, c1, c2);
            rec_step<0>(1.f, lane, gr[7 * G1 + lane], shs, w1p, wi2p, wh2p, bias2p,
                        cn1, ca1, cn2, ca2, c1, c2);
            rec_step<1>(1.f, lane, gr[8 * G1 + lane], shs, w1p, wi2p, wh2p, bias2p,
                        cn1, ca1, cn2, ca2, c1, c2);
            rec_step<0>(1.f, lane, gr[9 * G1 + lane], shs, w1p, wi2p, wh2p, bias2p,
                        cn1, ca1, cn2, ca2, c1, c2);
            BAR64();
        }

        // ---- epilogue: layer2(999) from shs[1] (x2(999), h2(998)) ----
        const ulonglong2* hp = reinterpret_cast<const ulonglong2*>(&shs[1][0]);
        ulonglong2 x01 = hp[2], x23 = hp[3], h2a = hp[4];
        u64 h2b = reinterpret_cast<const u64*>(&shs[1][0])[10];

        u64 P = fma2(x01.x, wi2p[0], bias2p);
        u64 Q = mul2(x01.y, wi2p[1]);
        P = fma2(x23.x, wi2p[2], P);
        Q = fma2(x23.y, wi2p[3], Q);
        P = fma2(h2a.x, wh2p[0], P);
        Q = fma2(h2a.y, wh2p[1], Q);
        P = fma2(h2b,   wh2p[2], P);
        float g2 = hadd2(add2(P, Q));

        float a2 = fmaf(cn2, tanha(g2), ca2);
        float s2 = shflx(a2, 16);
        float p2 = a2 * s2;
        float t2 = shflx(p2, 8);
        c2 = fmaf(a2, c2, t2);                 // lanes 8-13
        float tx = tanha(s2 * tanha(c2));      // tanh(h2(999)) at lanes 8-13

        float s = b_fc[0];
#pragma unroll
        for (int j = 0; j < H2; j++)
            s = fmaf(shflf(tx, 8 + j), W_fc[j], s);
        if (lane == 0)
            out[b] = fmaf(0.5f, tanha(0.5f * s), 0.5f);
    }
}

// ============================================================================
extern "C" void kernel_launch(void* const* d_in, const int* in_sizes, int n_in,
                              void* d_out, int out_size) {
    const float* x     = (const float*)d_in[0];
    const float* W_ih1 = (const float*)d_in[1];
    const float* W_hh1 = (const float*)d_in[2];
    const float* b_ih1 = (const float*)d_in[3];
    const float* b_hh1 = (const float*)d_in[4];
    const float* W_ih2 = (const float*)d_in[5];
    const float* W_hh2 = (const float*)d_in[6];
    const float* b_ih2 = (const float*)d_in[7];
    const float* b_hh2 = (const float*)d_in[8];
    const float* W_fc  = (const float*)d_in[9];
    const float* b_fc  = (const float*)d_in[10];
    float* out = (float*)d_out;

    fused_pc<<<BATCH, 64>>>(x, W_ih1, W_hh1, b_ih1, b_hh1,
                            W_ih2, W_hh2, b_ih2, b_hh2, W_fc, b_fc, out);
}